// round 4
// baseline (speedup 1.0000x reference)
#include <cuda_runtime.h>

#define TT   512
#define BB   1024
#define OBSN 64
#define HH   256
#define AA   16
#define BM   8
#define NCTA 128
#define KH   114      // W_h rows resident in SMEM; rows [KH,256) streamed from L2
#define HQP  12       // padded floats per h/obs row (8 data + 4 pad) -> LDS.128-friendly

// persistent transposed weights (allocation-free scratch)
__device__ float g_WhT[HH * HH];     // [k][j] = W_h[j][k]
__device__ float g_WiT[OBSN * HH];   // [k][j] = W_in[j][k]

__global__ void prep_kernel(const float* __restrict__ W_in,
                            const float* __restrict__ W_h) {
    int idx = blockIdx.x * blockDim.x + threadIdx.x;
    if (idx < HH * HH) {
        int k = idx / HH, j = idx % HH;
        g_WhT[idx] = W_h[j * HH + k];
    }
    if (idx < OBSN * HH) {
        int k = idx / HH, j = idx % HH;
        g_WiT[idx] = W_in[j * OBSN + k];
    }
}

typedef unsigned long long u64;

__device__ __forceinline__ u64 pack2(float lo, float hi) {
    u64 u; asm("mov.b64 %0,{%1,%2};" : "=l"(u) : "f"(lo), "f"(hi)); return u;
}
__device__ __forceinline__ void unpack2(u64 v, float& lo, float& hi) {
    asm("mov.b64 {%0,%1},%2;" : "=f"(lo), "=f"(hi) : "l"(v));
}
__device__ __forceinline__ void fma2(u64& d, u64 a, u64 b) {   // d += a*b (packed f32x2)
    asm("fma.rn.f32x2 %0,%1,%2,%0;" : "+l"(d) : "l"(a), "l"(b));
}
__device__ __forceinline__ void add2(u64& d, u64 a) {          // d += a (packed f32x2)
    asm("add.rn.f32x2 %0,%0,%1;" : "+l"(d) : "l"(a));
}
__device__ __forceinline__ float sigf(float x) {
    return __fdividef(1.0f, 1.0f + __expf(-x));
}

// one k-step: acc_r(j0) and acc_r(j1) += h[k][r] * w[k][j]
__device__ __forceinline__ void kstep(const float2 w, const float* hbase,
                                      u64 acc0[4], u64 acc1[4]) {
    u64 w0 = pack2(w.x, w.x), w1 = pack2(w.y, w.y);
    ulonglong2 q0 = *(const ulonglong2*)(hbase);       // rows 0-3 (as two f32x2)
    ulonglong2 q1 = *(const ulonglong2*)(hbase + 4);   // rows 4-7
    fma2(acc0[0], q0.x, w0); fma2(acc0[1], q0.y, w0);
    fma2(acc0[2], q1.x, w0); fma2(acc0[3], q1.y, w0);
    fma2(acc1[0], q0.x, w1); fma2(acc1[1], q0.y, w1);
    fma2(acc1[2], q1.x, w1); fma2(acc1[3], q1.y, w1);
}

__global__ void __launch_bounds__(256, 1) rnn_kernel(
    const float* __restrict__ obs,
    const float* __restrict__ b_h,
    const float* __restrict__ W_out,
    const float* __restrict__ b_out,
    float* __restrict__ out)
{
    extern __shared__ float sm[];
    float* s_hq   = sm;                       // [HH][HQP]    h, quad layout per j
    float* s_obsq = s_hq   + HH * HQP;        // [OBSN][HQP]  obs tile, same layout
    float* s_hT   = s_obsq + OBSN * HQP;      // [8][HH]      h transposed (for head)
    float* s_part = s_hT   + 8 * HH;          // 2048 floats  half1 partials
    float* s_Wo   = s_part + 2048;            // [AA][HH]     W_out as-is
    float* s_Wi   = s_Wo   + AA * HH;         // [OBSN][HH]   W_in^T
    float* s_Wh   = s_Wi   + OBSN * HH;       // [KH][HH]     W_h^T rows [0,KH)

    const int tid  = threadIdx.x;
    const int half = tid >> 7;                // 0: obs + W_h[0,96) ; 1: W_h[96,256)
    const int jp   = tid & 127;
    const int j0   = jp * 2;
    const int b0   = blockIdx.x * BM;

    // ---- one-time init ----
    for (int i = tid; i < HH * HQP;  i += 256) s_hq[i] = 0.0f;
    for (int i = tid; i < AA * HH;   i += 256) s_Wo[i] = W_out[i];
    for (int i = tid; i < OBSN * HH; i += 256) s_Wi[i] = g_WiT[i];
    for (int i = tid; i < KH * HH;   i += 256) s_Wh[i] = g_WhT[i];

    const float bh0 = b_h[j0], bh1 = b_h[j0 + 1];
    const int r_o = tid >> 4, a_o = tid & 15;          // head mapping (tid<128)
    float bo = (tid < 128) ? b_out[a_o] : 0.0f;
    float o_reg = 0.0f;

    // obs staging mapping (half1 threads): jp -> (k, row-quad)
    const int ko = jp & 63, rq = jp >> 6;

    if (half == 1) {   // stage obs for t=0
        float4 pf;
        pf.x = obs[((b0 + rq * 4 + 0) * TT + 0) * OBSN + ko];
        pf.y = obs[((b0 + rq * 4 + 1) * TT + 0) * OBSN + ko];
        pf.z = obs[((b0 + rq * 4 + 2) * TT + 0) * OBSN + ko];
        pf.w = obs[((b0 + rq * 4 + 3) * TT + 0) * OBSN + ko];
        *(float4*)(s_obsq + ko * HQP + rq * 4) = pf;
    }
    __syncthreads();

    for (int t = 0; t < TT; ++t) {
        u64 acc0[4], acc1[4];
        float4 pf;

        if (half == 0) {
            u64 i0 = pack2(bh0, bh0), i1 = pack2(bh1, bh1);
            acc0[0] = i0; acc0[1] = i0; acc0[2] = i0; acc0[3] = i0;
            acc1[0] = i1; acc1[1] = i1; acc1[2] = i1; acc1[3] = i1;

            const float* wp = s_Wi + j0;
            const float* hb = s_obsq;
            #pragma unroll 4
            for (int k = 0; k < OBSN; ++k) {
                kstep(*(const float2*)wp, hb, acc0, acc1);
                wp += HH; hb += HQP;
            }
            wp = s_Wh + j0; hb = s_hq;
            #pragma unroll 4
            for (int k = 0; k < 96; ++k) {
                kstep(*(const float2*)wp, hb, acc0, acc1);
                wp += HH; hb += HQP;
            }
        } else {
            // prefetch obs for t+1 (hidden behind the k-loop)
            int tn = (t + 1 < TT) ? t + 1 : t;
            pf.x = obs[((b0 + rq * 4 + 0) * TT + tn) * OBSN + ko];
            pf.y = obs[((b0 + rq * 4 + 1) * TT + tn) * OBSN + ko];
            pf.z = obs[((b0 + rq * 4 + 2) * TT + tn) * OBSN + ko];
            pf.w = obs[((b0 + rq * 4 + 3) * TT + tn) * OBSN + ko];

            acc0[0] = 0; acc0[1] = 0; acc0[2] = 0; acc0[3] = 0;
            acc1[0] = 0; acc1[1] = 0; acc1[2] = 0; acc1[3] = 0;

            const float* wp = s_Wh + 96 * HH + j0;
            const float* hb = s_hq + 96 * HQP;
            #pragma unroll 4
            for (int k = 96; k < KH; ++k) {
                kstep(*(const float2*)wp, hb, acc0, acc1);
                wp += HH; hb += HQP;
            }
            const float* wg = g_WhT + KH * HH + j0;   // streamed from L2
            #pragma unroll 8
            for (int k = KH; k < HH; ++k) {
                kstep(*(const float2*)wg, hb, acc0, acc1);
                wg += HH; hb += HQP;
            }
            // publish partials
            ulonglong2* pq = (ulonglong2*)s_part;
            pq[0 * 128 + jp] = make_ulonglong2(acc0[0], acc0[1]);
            pq[1 * 128 + jp] = make_ulonglong2(acc0[2], acc0[3]);
            pq[2 * 128 + jp] = make_ulonglong2(acc1[0], acc1[1]);
            pq[3 * 128 + jp] = make_ulonglong2(acc1[2], acc1[3]);
        }
        __syncthreads();   // sync_b: partials + last h/obs reads complete

        if (half == 0) {
            // combine halves
            const ulonglong2* pq = (const ulonglong2*)s_part;
            ulonglong2 p0 = pq[jp], p1 = pq[128 + jp], p2 = pq[256 + jp], p3 = pq[384 + jp];
            add2(acc0[0], p0.x); add2(acc0[1], p0.y);
            add2(acc0[2], p1.x); add2(acc0[3], p1.y);
            add2(acc1[0], p2.x); add2(acc1[1], p2.y);
            add2(acc1[2], p3.x); add2(acc1[3], p3.y);

            float p00,p01,p02,p03,p04,p05,p06,p07;
            float p10,p11,p12,p13,p14,p15,p16,p17;
            unpack2(acc0[0],p00,p01); unpack2(acc0[1],p02,p03);
            unpack2(acc0[2],p04,p05); unpack2(acc0[3],p06,p07);
            unpack2(acc1[0],p10,p11); unpack2(acc1[1],p12,p13);
            unpack2(acc1[2],p14,p15); unpack2(acc1[3],p16,p17);

            float4 a0 = *(float4*)(s_hq + j0 * HQP);
            float4 c0 = *(float4*)(s_hq + j0 * HQP + 4);
            float4 a1 = *(float4*)(s_hq + (j0 + 1) * HQP);
            float4 c1 = *(float4*)(s_hq + (j0 + 1) * HQP + 4);

            float h00 = 0.9f*a0.x + 0.1f*sigf(p00);
            float h01 = 0.9f*a0.y + 0.1f*sigf(p01);
            float h02 = 0.9f*a0.z + 0.1f*sigf(p02);
            float h03 = 0.9f*a0.w + 0.1f*sigf(p03);
            float h04 = 0.9f*c0.x + 0.1f*sigf(p04);
            float h05 = 0.9f*c0.y + 0.1f*sigf(p05);
            float h06 = 0.9f*c0.z + 0.1f*sigf(p06);
            float h07 = 0.9f*c0.w + 0.1f*sigf(p07);
            float h10 = 0.9f*a1.x + 0.1f*sigf(p10);
            float h11 = 0.9f*a1.y + 0.1f*sigf(p11);
            float h12 = 0.9f*a1.z + 0.1f*sigf(p12);
            float h13 = 0.9f*a1.w + 0.1f*sigf(p13);
            float h14 = 0.9f*c1.x + 0.1f*sigf(p14);
            float h15 = 0.9f*c1.y + 0.1f*sigf(p15);
            float h16 = 0.9f*c1.z + 0.1f*sigf(p16);
            float h17 = 0.9f*c1.w + 0.1f*sigf(p17);

            *(float4*)(s_hq + j0 * HQP)         = make_float4(h00,h01,h02,h03);
            *(float4*)(s_hq + j0 * HQP + 4)     = make_float4(h04,h05,h06,h07);
            *(float4*)(s_hq + (j0+1) * HQP)     = make_float4(h10,h11,h12,h13);
            *(float4*)(s_hq + (j0+1) * HQP + 4) = make_float4(h14,h15,h16,h17);

            *(float2*)(s_hT + 0*HH + j0) = make_float2(h00, h10);
            *(float2*)(s_hT + 1*HH + j0) = make_float2(h01, h11);
            *(float2*)(s_hT + 2*HH + j0) = make_float2(h02, h12);
            *(float2*)(s_hT + 3*HH + j0) = make_float2(h03, h13);
            *(float2*)(s_hT + 4*HH + j0) = make_float2(h04, h14);
            *(float2*)(s_hT + 5*HH + j0) = make_float2(h05, h15);
            *(float2*)(s_hT + 6*HH + j0) = make_float2(h06, h16);
            *(float2*)(s_hT + 7*HH + j0) = make_float2(h07, h17);
        } else {
            *(float4*)(s_obsq + ko * HQP + rq * 4) = pf;   // obs for t+1
        }
        __syncthreads();   // sync_c: new h (and next obs) visible

        // ---- output head: o[r][a] for the new h ----
        if (tid < 128) {
            const ulonglong2* hTa = (const ulonglong2*)(s_hT + r_o * HH);
            const ulonglong2* woa = (const ulonglong2*)(s_Wo + a_o * HH);
            u64 A0 = 0, A1 = 0;
            #pragma unroll 8
            for (int q = 0; q < 64; ++q) {
                ulonglong2 hv = hTa[q], wv = woa[q];
                fma2(A0, hv.x, wv.x); fma2(A1, hv.y, wv.y);
            }
            float f0,f1,f2,f3;
            unpack2(A0,f0,f1); unpack2(A1,f2,f3);
            float pre_o = bo + ((f0 + f1) + (f2 + f3));
            o_reg = 0.9f * o_reg + 0.1f * sigf(pre_o);
            out[((b0 + r_o) * TT + t) * AA + a_o] = o_reg;
        }
    }

    // ---- final states: [out | h | o] ----
    const long OUT_H = (long)BB * TT * AA;
    const long OUT_O = OUT_H + (long)BB * HH;
    if (half == 0) {
        #pragma unroll
        for (int r = 0; r < 8; ++r) {
            float hv0 = s_hq[j0 * HQP + r];
            float hv1 = s_hq[(j0 + 1) * HQP + r];
            *(float2*)(out + OUT_H + (long)(b0 + r) * HH + j0) = make_float2(hv0, hv1);
        }
    }
    if (tid < 128)
        out[OUT_O + (long)(b0 + r_o) * AA + a_o] = o_reg;
}

extern "C" void kernel_launch(void* const* d_in, const int* in_sizes, int n_in,
                              void* d_out, int out_size) {
    const float* obs   = (const float*)d_in[0];
    const float* W_in  = (const float*)d_in[1];
    const float* W_h   = (const float*)d_in[2];
    const float* b_h   = (const float*)d_in[3];
    const float* W_out = (const float*)d_in[4];
    const float* b_out = (const float*)d_in[5];
    float* out = (float*)d_out;

    prep_kernel<<<(HH * HH + 255) / 256, 256>>>(W_in, W_h);

    size_t shbytes = (size_t)(HH * HQP + OBSN * HQP + 8 * HH + 2048 +
                              AA * HH + OBSN * HH + KH * HH) * sizeof(float); // 230,400 B
    cudaFuncSetAttribute(rnn_kernel,
                         cudaFuncAttributeMaxDynamicSharedMemorySize, (int)shbytes);
    rnn_kernel<<<NCTA, 256, shbytes>>>(obs, b_h, W_out, b_out, out);
}

// round 5
// speedup vs baseline: 1.8274x; 1.8274x over previous
#include <cuda_runtime.h>
#include <cuda_fp16.h>

#define TT   512
#define BB   1024
#define OBSN 64
#define HH   256
#define AA   16
#define BM   8
#define NCTA 128
#define NTH  512
#define KTOT 320          // 64 obs rows + 256 h rows
#define SQP  12           // state row stride (floats): 8 data + 4 pad, 16B-aligned
#define WOP  260          // padded W_out row stride (floats)

// fused fp16 weights: rows [0,64) = W_in^T, rows [64,320) = W_h^T  ([k][j])
__device__ __half g_W16[KTOT * HH];

__global__ void prep_kernel(const float* __restrict__ W_in,
                            const float* __restrict__ W_h) {
    int idx = blockIdx.x * blockDim.x + threadIdx.x;
    if (idx < KTOT * HH) {
        int k = idx / HH, j = idx % HH;
        float v = (k < OBSN) ? W_in[j * OBSN + k] : W_h[j * HH + (k - OBSN)];
        g_W16[idx] = __float2half_rn(v);
    }
}

typedef unsigned long long u64;

__device__ __forceinline__ u64 pack2(float lo, float hi) {
    u64 u; asm("mov.b64 %0,{%1,%2};" : "=l"(u) : "f"(lo), "f"(hi)); return u;
}
__device__ __forceinline__ void unpack2(u64 v, float& lo, float& hi) {
    asm("mov.b64 {%0,%1},%2;" : "=f"(lo), "=f"(hi) : "l"(v));
}
__device__ __forceinline__ void fma2(u64& d, u64 a, u64 b) {   // packed f32x2 FMA
    asm("fma.rn.f32x2 %0,%1,%2,%0;" : "+l"(d) : "l"(a), "l"(b));
}
__device__ __forceinline__ void add2(u64& d, u64 a) {          // packed f32x2 add
    asm("add.rn.f32x2 %0,%0,%1;" : "+l"(d) : "l"(a));
}
__device__ __forceinline__ float sigf(float x) {
    return __fdividef(1.0f, 1.0f + __expf(-x));
}

__global__ void __launch_bounds__(NTH, 1) rnn_kernel(
    const float* __restrict__ obs,
    const float* __restrict__ b_h,
    const float* __restrict__ W_out,
    const float* __restrict__ b_out,
    float* __restrict__ out)
{
    extern __shared__ char smraw[];
    __half* s_W16  = (__half*)smraw;                          // 163,840 B
    float*  s_state = (float*)(smraw + KTOT * HH * 2);        // [KTOT][SQP] 15,360 B
    float*  s_hT    = s_state + KTOT * SQP;                   // [8][HH]      8,192 B
    float*  s_part  = s_hT + 8 * HH;                          // 12*128 ull2 24,576 B
    float*  s_Wo    = s_part + 12 * 128 * 4;                  // [AA][WOP]   16,640 B
    float*  s_h     = s_state + OBSN * SQP;                   // h rows base

    const int tid   = threadIdx.x;
    const int slice = tid >> 7;          // 0..3
    const int jp    = tid & 127;
    const int j0    = jp * 2;
    const int b0    = blockIdx.x * BM;

    // k-range per slice: {56, 88, 88, 88}; slice0 also runs combine/update/head
    const int kb = (slice == 0) ? 0 : 56 + (slice - 1) * 88;
    const int kc = (slice == 0) ? 56 : 88;

    // ---- one-time init ----
    for (int i = tid; i < KTOT * HH / 8; i += NTH)
        ((uint4*)s_W16)[i] = ((const uint4*)g_W16)[i];
    for (int i = tid; i < HH * SQP; i += NTH) s_h[i] = 0.0f;
    for (int i = tid; i < AA * HH; i += NTH)
        s_Wo[(i >> 8) * WOP + (i & 255)] = W_out[i];

    const float bh0 = (slice == 0) ? b_h[j0] : 0.0f;
    const float bh1 = (slice == 0) ? b_h[j0 + 1] : 0.0f;
    const int r_o = tid >> 4, a_o = tid & 15;      // head mapping (tid<128)
    float bo = (tid < 128) ? b_out[a_o] : 0.0f;
    float o_reg = 0.0f;

    const int ko = jp & 63, rq = jp >> 6;          // obs staging map (slice1)
    if (slice == 1) {                              // stage obs for t=0
        float4 p0;
        p0.x = obs[((b0 + rq * 4 + 0) * TT + 0) * OBSN + ko];
        p0.y = obs[((b0 + rq * 4 + 1) * TT + 0) * OBSN + ko];
        p0.z = obs[((b0 + rq * 4 + 2) * TT + 0) * OBSN + ko];
        p0.w = obs[((b0 + rq * 4 + 3) * TT + 0) * OBSN + ko];
        *(float4*)(s_state + ko * SQP + rq * 4) = p0;
    }
    __syncthreads();

    for (int t = 0; t < TT; ++t) {
        u64 acc0[4], acc1[4];
        {
            u64 i0 = pack2(bh0, bh0), i1 = pack2(bh1, bh1);
            acc0[0]=i0; acc0[1]=i0; acc0[2]=i0; acc0[3]=i0;
            acc1[0]=i1; acc1[1]=i1; acc1[2]=i1; acc1[3]=i1;
        }

        float4 pf;
        if (slice == 1) {                          // prefetch obs t+1 (hidden under k-loop)
            int tn = (t + 1 < TT) ? t + 1 : t;
            pf.x = obs[((b0 + rq * 4 + 0) * TT + tn) * OBSN + ko];
            pf.y = obs[((b0 + rq * 4 + 1) * TT + tn) * OBSN + ko];
            pf.z = obs[((b0 + rq * 4 + 2) * TT + tn) * OBSN + ko];
            pf.w = obs[((b0 + rq * 4 + 3) * TT + tn) * OBSN + ko];
        }

        // ---- k-slice GEMM: acc[j][r] += state[k][r] * W16[k][j] ----
        const __half2* wrow = (const __half2*)s_W16 + kb * (HH / 2) + jp;
        const float*   st   = s_state + kb * SQP;
        #pragma unroll 8
        for (int k = 0; k < kc; ++k) {
            float2 w = __half22float2(*wrow);
            u64 w0 = pack2(w.x, w.x), w1 = pack2(w.y, w.y);
            ulonglong2 q0 = *(const ulonglong2*)(st);      // rows 0-3
            ulonglong2 q1 = *(const ulonglong2*)(st + 4);  // rows 4-7
            fma2(acc0[0], q0.x, w0); fma2(acc0[1], q0.y, w0);
            fma2(acc0[2], q1.x, w0); fma2(acc0[3], q1.y, w0);
            fma2(acc1[0], q0.x, w1); fma2(acc1[1], q0.y, w1);
            fma2(acc1[2], q1.x, w1); fma2(acc1[3], q1.y, w1);
            wrow += HH / 2; st += SQP;
        }

        if (slice != 0) {                          // publish partials (j0,j1 paired)
            ulonglong2* pq = (ulonglong2*)s_part;
            const int si = slice - 1;
            pq[(0 * 3 + si) * 128 + jp] = make_ulonglong2(acc0[0], acc1[0]);
            pq[(1 * 3 + si) * 128 + jp] = make_ulonglong2(acc0[1], acc1[1]);
            pq[(2 * 3 + si) * 128 + jp] = make_ulonglong2(acc0[2], acc1[2]);
            pq[(3 * 3 + si) * 128 + jp] = make_ulonglong2(acc0[3], acc1[3]);
        }
        __syncthreads();                           // sync_b

        if (slice == 0) {
            // ---- combine 4 slices ----
            const ulonglong2* pq = (const ulonglong2*)s_part;
            #pragma unroll
            for (int rp = 0; rp < 4; ++rp) {
                ulonglong2 v0 = pq[(rp * 3 + 0) * 128 + jp];
                ulonglong2 v1 = pq[(rp * 3 + 1) * 128 + jp];
                ulonglong2 v2 = pq[(rp * 3 + 2) * 128 + jp];
                add2(acc0[rp], v0.x); add2(acc1[rp], v0.y);
                add2(acc0[rp], v1.x); add2(acc1[rp], v1.y);
                add2(acc0[rp], v2.x); add2(acc1[rp], v2.y);
            }
            float p00,p01,p02,p03,p04,p05,p06,p07;
            float p10,p11,p12,p13,p14,p15,p16,p17;
            unpack2(acc0[0],p00,p01); unpack2(acc0[1],p02,p03);
            unpack2(acc0[2],p04,p05); unpack2(acc0[3],p06,p07);
            unpack2(acc1[0],p10,p11); unpack2(acc1[1],p12,p13);
            unpack2(acc1[2],p14,p15); unpack2(acc1[3],p16,p17);

            float4 a0 = *(float4*)(s_h + j0 * SQP);
            float4 c0 = *(float4*)(s_h + j0 * SQP + 4);
            float4 a1 = *(float4*)(s_h + (j0 + 1) * SQP);
            float4 c1 = *(float4*)(s_h + (j0 + 1) * SQP + 4);

            float h00 = 0.9f*a0.x + 0.1f*sigf(p00);
            float h01 = 0.9f*a0.y + 0.1f*sigf(p01);
            float h02 = 0.9f*a0.z + 0.1f*sigf(p02);
            float h03 = 0.9f*a0.w + 0.1f*sigf(p03);
            float h04 = 0.9f*c0.x + 0.1f*sigf(p04);
            float h05 = 0.9f*c0.y + 0.1f*sigf(p05);
            float h06 = 0.9f*c0.z + 0.1f*sigf(p06);
            float h07 = 0.9f*c0.w + 0.1f*sigf(p07);
            float h10 = 0.9f*a1.x + 0.1f*sigf(p10);
            float h11 = 0.9f*a1.y + 0.1f*sigf(p11);
            float h12 = 0.9f*a1.z + 0.1f*sigf(p12);
            float h13 = 0.9f*a1.w + 0.1f*sigf(p13);
            float h14 = 0.9f*c1.x + 0.1f*sigf(p14);
            float h15 = 0.9f*c1.y + 0.1f*sigf(p15);
            float h16 = 0.9f*c1.z + 0.1f*sigf(p16);
            float h17 = 0.9f*c1.w + 0.1f*sigf(p17);

            *(float4*)(s_h + j0 * SQP)           = make_float4(h00,h01,h02,h03);
            *(float4*)(s_h + j0 * SQP + 4)       = make_float4(h04,h05,h06,h07);
            *(float4*)(s_h + (j0 + 1) * SQP)     = make_float4(h10,h11,h12,h13);
            *(float4*)(s_h + (j0 + 1) * SQP + 4) = make_float4(h14,h15,h16,h17);

            *(float2*)(s_hT + 0*HH + j0) = make_float2(h00, h10);
            *(float2*)(s_hT + 1*HH + j0) = make_float2(h01, h11);
            *(float2*)(s_hT + 2*HH + j0) = make_float2(h02, h12);
            *(float2*)(s_hT + 3*HH + j0) = make_float2(h03, h13);
            *(float2*)(s_hT + 4*HH + j0) = make_float2(h04, h14);
            *(float2*)(s_hT + 5*HH + j0) = make_float2(h05, h15);
            *(float2*)(s_hT + 6*HH + j0) = make_float2(h06, h16);
            *(float2*)(s_hT + 7*HH + j0) = make_float2(h07, h17);
        } else if (slice == 1) {
            *(float4*)(s_state + ko * SQP + rq * 4) = pf;    // obs for t+1
        }
        __syncthreads();                           // sync_c

        // ---- output head on slice0; slices1-3 race ahead into next k-loop ----
        if (tid < 128) {
            const ulonglong2* hTa = (const ulonglong2*)(s_hT + r_o * HH);
            const ulonglong2* woa = (const ulonglong2*)(s_Wo + a_o * WOP);
            u64 A0 = 0, A1 = 0;
            #pragma unroll 8
            for (int q = 0; q < 64; ++q) {
                ulonglong2 hv = hTa[q], wv = woa[q];
                fma2(A0, hv.x, wv.x); fma2(A1, hv.y, wv.y);
            }
            float f0,f1,f2,f3;
            unpack2(A0,f0,f1); unpack2(A1,f2,f3);
            float pre_o = bo + ((f0 + f1) + (f2 + f3));
            o_reg = 0.9f * o_reg + 0.1f * sigf(pre_o);
            out[((b0 + r_o) * TT + t) * AA + a_o] = o_reg;
        }
    }

    // ---- final states: [out | h | o] ----
    const long OUT_H = (long)BB * TT * AA;
    const long OUT_O = OUT_H + (long)BB * HH;
    if (slice == 0) {
        #pragma unroll
        for (int r = 0; r < 8; ++r) {
            float hv0 = s_h[j0 * SQP + r];
            float hv1 = s_h[(j0 + 1) * SQP + r];
            *(float2*)(out + OUT_H + (long)(b0 + r) * HH + j0) = make_float2(hv0, hv1);
        }
    }
    if (tid < 128)
        out[OUT_O + (long)(b0 + r_o) * AA + a_o] = o_reg;
}

extern "C" void kernel_launch(void* const* d_in, const int* in_sizes, int n_in,
                              void* d_out, int out_size) {
    const float* obs   = (const float*)d_in[0];
    const float* W_in  = (const float*)d_in[1];
    const float* W_h   = (const float*)d_in[2];
    const float* b_h   = (const float*)d_in[3];
    const float* W_out = (const float*)d_in[4];
    const float* b_out = (const float*)d_in[5];
    float* out = (float*)d_out;

    prep_kernel<<<(KTOT * HH + 255) / 256, 256>>>(W_in, W_h);

    size_t shbytes = (size_t)KTOT * HH * 2                       // fp16 weights
                   + (size_t)(KTOT * SQP + 8 * HH + 12 * 128 * 4 // state + hT + partials
                              + AA * WOP) * sizeof(float);       // = 228,608 B
    cudaFuncSetAttribute(rnn_kernel,
                         cudaFuncAttributeMaxDynamicSharedMemorySize, (int)shbytes);
    rnn_kernel<<<NCTA, NTH, shbytes>>>(obs, b_h, W_out, b_out, out);
}